// round 13
// baseline (speedup 1.0000x reference)
#include <cuda_runtime.h>

// Embed3D: out[nl, p*40 + 2k + {0,1}] = {sin, cos}(x[nl,1+p] * div_term[k])
// x: (NL,4) fp32, div_term: 20 fp32, out: (NL,120) fp32, NL = 64*8192 = 524288.
//
// Champion recipe (R10: blockDim=480, j=tid%30, r=tid/30, 8 slices of 16 rows,
// front-batched LDGs, contiguous STG.128 .cs, 4 CTA/SM) with TWO sequential
// 128-row tiles per block (grid 2048): halves per-block prologue/launch cost
// without raising live-register pressure (pos[8] reused per tile).

#define THREADS 480
#define ROWS_PER_SLICE 16
#define SLICES 8
#define ROWS_PER_TILE (ROWS_PER_SLICE * SLICES)   // 128
#define TILES_PER_BLOCK 2

__device__ __forceinline__ void stg_cs_v4(float4* ptr, float4 v) {
    asm volatile("st.global.cs.v4.f32 [%0], {%1, %2, %3, %4};"
                 :: "l"(ptr), "f"(v.x), "f"(v.y), "f"(v.z), "f"(v.w)
                 : "memory");
}

__global__ __launch_bounds__(THREADS, 4)
void embed3d_kernel(const float* __restrict__ x,
                    const float* __restrict__ div_term,
                    float* __restrict__ out,
                    int total_nl) {
    const int tid = threadIdx.x;
    const int j   = tid % 30;          // float4 slot within a row
    const int r   = tid / 30;          // row within slice (0..15)

    const int p = j / 10;              // pos component 0..2
    const int q = j - p * 10;          // pair group 0..9

    const float d0 = __ldg(&div_term[2 * q]);
    const float d1 = __ldg(&div_term[2 * q + 1]);

#pragma unroll
    for (int t = 0; t < TILES_PER_BLOCK; t++) {
        const int nl_base =
            (blockIdx.x * TILES_PER_BLOCK + t) * ROWS_PER_TILE + r;

        // Batch pos loads: 8 independent LDGs in flight.
        float pos[SLICES];
#pragma unroll
        for (int s = 0; s < SLICES; s++) {
            const int nl = nl_base + s * ROWS_PER_SLICE;
            pos[s] = __ldg(&x[nl * 4 + 1 + p]);
        }

#pragma unroll
        for (int s = 0; s < SLICES; s++) {
            const int nl = nl_base + s * ROWS_PER_SLICE;
            float4 v;
            __sincosf(pos[s] * d0, &v.x, &v.y);
            __sincosf(pos[s] * d1, &v.z, &v.w);
            stg_cs_v4(reinterpret_cast<float4*>(out) + nl * 30 + j, v);
        }
    }
}

extern "C" void kernel_launch(void* const* d_in, const int* in_sizes, int n_in,
                              void* d_out, int out_size) {
    const float* x        = (const float*)d_in[0];
    const float* div_term = (const float*)d_in[1];
    float* out            = (float*)d_out;

    const int total_nl = in_sizes[0] / 4;   // 524288, divisible by 256
    const int grid = total_nl / (ROWS_PER_TILE * TILES_PER_BLOCK);   // 2048

    embed3d_kernel<<<grid, THREADS>>>(x, div_term, out, total_nl);
}

// round 14
// speedup vs baseline: 1.0248x; 1.0248x over previous
#include <cuda_runtime.h>

// Embed3D: out[nl, p*40 + 2k + {0,1}] = {sin, cos}(x[nl,1+p] * div_term[k])
// x: (NL,4) fp32, div_term: 20 fp32, out: (NL,120) fp32, NL = 64*8192 = 524288.
//
// FINAL (champion, R10): blockDim=480 (15 full warps), each thread owns float4
// slot j = tid%30 in rows r, r+16, ..., r+112 (8 slices, 128 rows/block,
// grid 4096). Contiguous STG.128 per slice (global float4 index = nl*30 + j)
// with .cs evict-first (252MB zero-reuse write stream). Front-batched pos
// loads give 8-deep MLP; 8 independent sincos/store chains give ILP.
// __launch_bounds__(480,4) pins 4 CTA/SM (60 warps).
//
// Steady-state: ~6.7 TB/s (~84% of HBM spec) on a 97%-write stream — at the
// practical HBM write ceiling. Falsified alternatives: TMA bulk store (-21us),
// persistent 1-wave grid (-4.5us), STG.256 (-4us, x2), 960-thread blocks
// (neutral), 2 tiles/block (-0.9us).

#define THREADS 480
#define ROWS_PER_SLICE 16
#define SLICES 8
#define ROWS_PER_BLOCK (ROWS_PER_SLICE * SLICES)   // 128

__device__ __forceinline__ void stg_cs_v4(float4* ptr, float4 v) {
    asm volatile("st.global.cs.v4.f32 [%0], {%1, %2, %3, %4};"
                 :: "l"(ptr), "f"(v.x), "f"(v.y), "f"(v.z), "f"(v.w)
                 : "memory");
}

__global__ __launch_bounds__(THREADS, 4)
void embed3d_kernel(const float* __restrict__ x,
                    const float* __restrict__ div_term,
                    float* __restrict__ out,
                    int total_nl) {
    const int tid = threadIdx.x;
    const int j   = tid % 30;          // float4 slot within a row
    const int r   = tid / 30;          // row within slice (0..15)

    const int p = j / 10;              // pos component 0..2
    const int q = j - p * 10;          // pair group 0..9

    const float d0 = __ldg(&div_term[2 * q]);
    const float d1 = __ldg(&div_term[2 * q + 1]);

    const int nl_base = blockIdx.x * ROWS_PER_BLOCK + r;

    // Batch all pos loads up front: 8 independent LDGs in flight.
    float pos[SLICES];
#pragma unroll
    for (int s = 0; s < SLICES; s++) {
        const int nl = nl_base + s * ROWS_PER_SLICE;
        pos[s] = __ldg(&x[nl * 4 + 1 + p]);
    }

#pragma unroll
    for (int s = 0; s < SLICES; s++) {
        const int nl = nl_base + s * ROWS_PER_SLICE;
        float4 v;
        __sincosf(pos[s] * d0, &v.x, &v.y);
        __sincosf(pos[s] * d1, &v.z, &v.w);
        stg_cs_v4(reinterpret_cast<float4*>(out) + nl * 30 + j, v);
    }
}

extern "C" void kernel_launch(void* const* d_in, const int* in_sizes, int n_in,
                              void* d_out, int out_size) {
    const float* x        = (const float*)d_in[0];
    const float* div_term = (const float*)d_in[1];
    float* out            = (float*)d_out;

    const int total_nl = in_sizes[0] / 4;   // 524288, divisible by 128
    const int grid = total_nl / ROWS_PER_BLOCK;   // 4096

    embed3d_kernel<<<grid, THREADS>>>(x, div_term, out, total_nl);
}